// round 1
// baseline (speedup 1.0000x reference)
#include <cuda_runtime.h>
#include <math.h>

#define BSZ 2048
#define ND 128
#define HID 256
#define SHD 64
#define NSTEPS 8
#define MROWS 16
#define NBLOCKS (BSZ / MROWS)
#define NTHR 256

typedef unsigned long long ull;

// ---------- packed f32x2 helpers (double-rate FMA path on sm_103a) ----------
__device__ __forceinline__ void fma2(ull &c, ull a, ull b) {
    asm("fma.rn.f32x2 %0, %1, %2, %3;" : "=l"(c) : "l"(a), "l"(b), "l"(c));
}
__device__ __forceinline__ ull packdup(float x) {
    ull r; asm("mov.b64 %0, {%1, %2};" : "=l"(r) : "f"(x), "f"(x)); return r;
}
__device__ __forceinline__ void unpack2(ull v, float &x, float &y) {
    asm("mov.b64 {%0, %1}, %2;" : "=f"(x), "=f"(y) : "l"(v));
}

// ---------- swizzled transposed shared buffers: row r holds 16 M-values ----------
// logical float4-chunk t of row r lives at physical chunk (t ^ ((r>>1)&3)).
// -> broadcast LDS.128 reads conflict-free; per-thread row writes conflict-free.
__device__ __forceinline__ float4 ldchunk(const float* buf, int r, int t) {
    return reinterpret_cast<const float4*>(buf + r * 16)[t ^ ((r >> 1) & 3)];
}
__device__ __forceinline__ void stchunk(float* buf, int r, int t, float4 v) {
    reinterpret_cast<float4*>(buf + r * 16)[t ^ ((r >> 1) & 3)] = v;
}
__device__ __forceinline__ void load_row(const float* buf, int r, float v[16]) {
    #pragma unroll
    for (int t = 0; t < 4; ++t) {
        float4 c = ldchunk(buf, r, t);
        v[4*t+0] = c.x; v[4*t+1] = c.y; v[4*t+2] = c.z; v[4*t+3] = c.w;
    }
}
__device__ __forceinline__ void store_row(float* buf, int r, const float v[16]) {
    #pragma unroll
    for (int t = 0; t < 4; ++t)
        stchunk(buf, r, t, make_float4(v[4*t+0], v[4*t+1], v[4*t+2], v[4*t+3]));
}

__device__ __forceinline__ float softplus_f(float x) {
    return fmaxf(x, 0.f) + log1pf(expf(-fabsf(x)));
}
__device__ __forceinline__ float san(float x) { return isfinite(x) ? x : 0.f; }

// deterministic reduction over threads 0..127 (16 per-row partials each)
__device__ __forceinline__ void reduce128(float sq[16], float* red, float* out16, int tid) {
    if (tid < 128) {
        #pragma unroll
        for (int off = 16; off > 0; off >>= 1) {
            #pragma unroll
            for (int m = 0; m < 16; ++m)
                sq[m] += __shfl_down_sync(0xffffffffu, sq[m], off);
        }
        if ((tid & 31) == 0) {
            int w = tid >> 5;
            #pragma unroll
            for (int m = 0; m < 16; ++m) red[w * 16 + m] = sq[m];
        }
    }
    __syncthreads();
    if (tid < 16)
        out16[tid] = red[tid] + red[16 + tid] + red[32 + tid] + red[48 + tid];
}

// ---------- block GEMM: out[16 x N] = act(in[16 x K] @ W[K x N] + bias) ----------
// thread = (col j, k-slice s); 16 row-accumulators as 8 f32x2 pairs.
// ACT: 0 none, 1 tanh, 2 softplus, 3 relu
template<int K, int N, int S, int ACT, bool WRITE>
__device__ __forceinline__ void gemm(const float* __restrict__ Wg,
                                     const float* __restrict__ bias,
                                     const float* in_buf, float* out_buf,
                                     float* cb, int tid, float vout[16]) {
    const int j = tid % N;
    const int s = tid / N;
    const int KS = K / S;
    const int k0 = s * KS;
    ull acc[8];
    #pragma unroll
    for (int p = 0; p < 8; ++p) acc[p] = 0ULL;
    const float* __restrict__ wp = Wg + (size_t)k0 * N + j;
    #pragma unroll 8
    for (int kk = 0; kk < KS; ++kk) {
        int k = k0 + kk;
        float w = wp[(size_t)kk * N];
        ull w2 = packdup(w);
        const ulonglong2* row = reinterpret_cast<const ulonglong2*>(in_buf + k * 16);
        int sw = (k >> 1) & 3;
        ulonglong2 p0 = row[0 ^ sw];
        ulonglong2 p1 = row[1 ^ sw];
        ulonglong2 p2 = row[2 ^ sw];
        ulonglong2 p3 = row[3 ^ sw];
        fma2(acc[0], p0.x, w2); fma2(acc[1], p0.y, w2);
        fma2(acc[2], p1.x, w2); fma2(acc[3], p1.y, w2);
        fma2(acc[4], p2.x, w2); fma2(acc[5], p2.y, w2);
        fma2(acc[6], p3.x, w2); fma2(acc[7], p3.y, w2);
    }
    float v[16];
    #pragma unroll
    for (int p = 0; p < 8; ++p) unpack2(acc[p], v[2*p], v[2*p+1]);
    if (S > 1) {
        if (s > 0) store_row(cb, (s - 1) * N + j, v);
        __syncthreads();
        if (s == 0) {
            #pragma unroll
            for (int ss = 1; ss < S; ++ss) {
                float w16[16];
                load_row(cb, (ss - 1) * N + j, w16);
                #pragma unroll
                for (int m = 0; m < 16; ++m) v[m] += w16[m];
            }
        }
    }
    if (s == 0) {
        float b = (bias != nullptr) ? bias[j] : 0.f;
        #pragma unroll
        for (int m = 0; m < 16; ++m) {
            float x = v[m] + b;
            if (ACT == 1)      x = tanhf(x);
            else if (ACT == 2) x = softplus_f(x);
            else if (ACT == 3) x = fmaxf(x, 0.f);
            v[m] = x;
        }
        if (WRITE) store_row(out_buf, j, v);
        #pragma unroll
        for (int m = 0; m < 16; ++m) vout[m] = v[m];
    }
}

// ---------- Jacobian contraction: r[16 x 128] = u[16 x 128] @ kw^T, reduced ----------
// DOT=false: out16[m] = sum_j r[m][j]^2 ; DOT=true: out16[m] = sum_j k[m][j]*r[m][j]
template<bool DOT>
__device__ __forceinline__ void jac_gemm(const float* kwt, const float* ub,
                                         const float* kob, float* cb,
                                         float* red, float* out16, int tid) {
    const int j = tid & 127, s = tid >> 7;
    ull acc[8];
    #pragma unroll
    for (int p = 0; p < 8; ++p) acc[p] = 0ULL;
    const int i0 = s * 64;
    #pragma unroll 8
    for (int ii = 0; ii < 64; ++ii) {
        int i = i0 + ii;
        float w = kwt[j * 129 + i];   // kw[i][j], padded: conflict-free
        ull w2 = packdup(w);
        const ulonglong2* row = reinterpret_cast<const ulonglong2*>(ub + i * 16);
        int sw = (i >> 1) & 3;
        ulonglong2 p0 = row[0 ^ sw];
        ulonglong2 p1 = row[1 ^ sw];
        ulonglong2 p2 = row[2 ^ sw];
        ulonglong2 p3 = row[3 ^ sw];
        fma2(acc[0], p0.x, w2); fma2(acc[1], p0.y, w2);
        fma2(acc[2], p1.x, w2); fma2(acc[3], p1.y, w2);
        fma2(acc[4], p2.x, w2); fma2(acc[5], p2.y, w2);
        fma2(acc[6], p3.x, w2); fma2(acc[7], p3.y, w2);
    }
    float v[16];
    #pragma unroll
    for (int p = 0; p < 8; ++p) unpack2(acc[p], v[2*p], v[2*p+1]);
    if (s == 1) store_row(cb, j, v);
    __syncthreads();
    float sq[16];
    #pragma unroll
    for (int m = 0; m < 16; ++m) sq[m] = 0.f;
    if (s == 0) {
        float w16[16];
        load_row(cb, j, w16);
        if (DOT) {
            float kr[16];
            load_row(kob, j, kr);
            #pragma unroll
            for (int m = 0; m < 16; ++m) sq[m] = (v[m] + w16[m]) * kr[m];
        } else {
            #pragma unroll
            for (int m = 0; m < 16; ++m) { float x = v[m] + w16[m]; sq[m] = x * x; }
        }
    }
    reduce128(sq, red, out16, tid);
}

// elementwise u = (1 - k^2) * src, over [128 rows][16 m]
__device__ __forceinline__ void compute_u(const float* kob, const float* src,
                                          float* ub, int tid) {
    int j = tid & 127, h = tid >> 7;
    #pragma unroll
    for (int tt = 0; tt < 2; ++tt) {
        int t2 = 2 * h + tt;
        float4 kv = ldchunk(kob, j, t2);
        float4 fv = ldchunk(src, j, t2);
        float4 uv;
        uv.x = (1.f - kv.x * kv.x) * fv.x;
        uv.y = (1.f - kv.y * kv.y) * fv.y;
        uv.z = (1.f - kv.z * kv.z) * fv.z;
        uv.w = (1.f - kv.w * kv.w) * fv.w;
        stchunk(ub, j, t2, uv);
    }
}

__global__ void __launch_bounds__(NTHR, 1)
node_kernel(const float* __restrict__ y0, const float* __restrict__ tv,
            const float* __restrict__ noise,
            const float* __restrict__ fw1, const float* __restrict__ fb1,
            const float* __restrict__ fw2, const float* __restrict__ fb2,
            const float* __restrict__ fw3, const float* __restrict__ fb3,
            const float* __restrict__ amw1, const float* __restrict__ amb1,
            const float* __restrict__ amw2, const float* __restrict__ amb2,
            const float* __restrict__ amw3, const float* __restrict__ amb3,
            const float* __restrict__ alw1, const float* __restrict__ alb1,
            const float* __restrict__ alw2, const float* __restrict__ alb2,
            const float* __restrict__ alw3, const float* __restrict__ alb3,
            const float* __restrict__ kw, float* __restrict__ out)
{
    extern __shared__ float smem[];
    float* kwt  = smem;              // 128*129 = 16512
    float* xs   = kwt + 16512;       // 2048  (x, transposed [128][16])
    float* h1   = xs + 2048;         // 4096  [256][16]
    float* h2   = h1 + 4096;         // 4096
    float* fo   = h2 + 4096;         // 2048
    float* ko   = fo + 2048;         // 2048
    float* mo   = ko + 2048;         // 2048
    float* lso  = mo + 2048;         // 2048
    float* go   = lso + 2048;        // 2048
    float* ub   = go + 2048;         // 2048
    float* a1   = ub + 2048;         // 1024  [64][16]
    float* a2   = a1 + 1024;         // 1024
    float* cb   = a2 + 1024;         // 3072  slice-combine scratch [192][16]
    float* red  = cb + 3072;         // 64
    float* kn2s = red + 64;          // 16
    float* jf2s = kn2s + 16;         // 16
    float* c2s  = jf2s + 16;         // 16
    float* scl  = c2s + 16;          // 16

    const int tid = threadIdx.x;
    const int r0 = blockIdx.x * MROWS;
    const float dt = tv[1] - tv[0];

    // stage kw^T into shared (padded rows of 129 -> conflict-free column reads)
    for (int idx = tid; idx < ND * ND; idx += NTHR) {
        int i = idx >> 7, jj = idx & 127;
        kwt[jj * 129 + i] = kw[idx];
    }
    // load y0 tile into xs (transposed+swizzled); emit output step 0
    {
        int j = tid & 127, h = tid >> 7;
        #pragma unroll
        for (int tt = 0; tt < 2; ++tt) {
            int t2 = 2 * h + tt;
            float a[4];
            #pragma unroll
            for (int q = 0; q < 4; ++q) {
                int m = 4 * t2 + q;
                float val = y0[(size_t)(r0 + m) * ND + j];
                out[(size_t)(r0 + m) * ND + j] = val;
                a[q] = val;
            }
            stchunk(xs, j, t2, make_float4(a[0], a[1], a[2], a[3]));
        }
    }
    __syncthreads();

    float vout[16];
    for (int step = 0; step < NSTEPS; ++step) {
        // ---- f_ode ----
        gemm<ND, HID, 1, 1, true>(fw1, fb1, xs, h1, cb, tid, vout); __syncthreads();
        gemm<HID, HID, 1, 2, true>(fw2, fb2, h1, h2, cb, tid, vout); __syncthreads();
        gemm<HID, ND, 2, 0, true>(fw3, fb3, h2, fo, cb, tid, vout); __syncthreads();
        // ---- k = tanh(x @ kw), plus ||k||^2 ----
        gemm<ND, ND, 2, 1, true>(kw, nullptr, xs, ko, cb, tid, vout);
        {
            float sq[16];
            #pragma unroll
            for (int m = 0; m < 16; ++m) sq[m] = 0.f;
            if (tid < 128) {
                #pragma unroll
                for (int m = 0; m < 16; ++m) sq[m] = vout[m] * vout[m];
            }
            reduce128(sq, red, kn2s, tid);
        }
        __syncthreads();
        // ---- actor mean path ----
        gemm<ND, SHD, 4, 3, true>(amw1, amb1, xs, a1, cb, tid, vout); __syncthreads();
        gemm<SHD, SHD, 4, 3, true>(amw2, amb2, a1, a2, cb, tid, vout); __syncthreads();
        gemm<SHD, ND, 2, 1, true>(amw3, amb3, a2, mo, cb, tid, vout); __syncthreads();
        // ---- actor log-std path ----
        gemm<ND, SHD, 4, 3, true>(alw1, alb1, xs, a1, cb, tid, vout); __syncthreads();
        gemm<SHD, SHD, 4, 3, true>(alw2, alb2, a1, a2, cb, tid, vout); __syncthreads();
        gemm<SHD, ND, 2, 0, true>(alw3, alb3, a2, lso, cb, tid, vout); __syncthreads();
        // ---- g = tanh(san(m) + softplus(san(ls)) * eps) ----
        {
            int j = tid & 127, h = tid >> 7;
            const float* np = noise + (size_t)step * BSZ * ND + (size_t)r0 * ND + j;
            #pragma unroll
            for (int tt = 0; tt < 2; ++tt) {
                int t2 = 2 * h + tt;
                float4 mv = ldchunk(mo, j, t2);
                float4 lv = ldchunk(lso, j, t2);
                float a[4] = {mv.x, mv.y, mv.z, mv.w};
                float l[4] = {lv.x, lv.y, lv.z, lv.w};
                float g[4];
                #pragma unroll
                for (int q = 0; q < 4; ++q) {
                    int m = 4 * t2 + q;
                    float sd = softplus_f(san(l[q]));
                    float e = np[(size_t)m * ND];
                    g[q] = tanhf(san(a[q]) + sd * e);
                }
                stchunk(go, j, t2, make_float4(g[0], g[1], g[2], g[3]));
            }
        }
        __syncthreads();
        // ---- ||Jf||^2 : u = (1-k^2)*f, then u @ kw^T reduced ----
        compute_u(ko, fo, ub, tid); __syncthreads();
        jac_gemm<false>(kwt, ub, nullptr, cb, red, jf2s, tid); __syncthreads();
        // ---- k . Jg : u = (1-k^2)*g ----
        compute_u(ko, go, ub, tid); __syncthreads();
        jac_gemm<true>(kwt, ub, ko, cb, red, c2s, tid); __syncthreads();
        // ---- mask -> per-row Euler scale ----
        if (tid < 16) {
            float kn2 = kn2s[tid];
            float kn = sqrtf(kn2);
            float jfn = sqrtf(jf2s[tid]);
            float kn9 = kn2 * kn2 * kn2 * kn2 * kn;
            float c1 = jfn - 60.0f * kn9;
            float c2 = c2s[tid] - 20.0f * kn9 * kn;
            bool mask = (c1 > 1e-8f) || (c2 < -1e-8f);
            scl[tid] = mask ? (0.5f * dt) : dt;
        }
        __syncthreads();
        // ---- Euler update + output write ----
        {
            int j = tid & 127, h = tid >> 7;
            float* ob = out + (size_t)(step + 1) * BSZ * ND;
            #pragma unroll
            for (int tt = 0; tt < 2; ++tt) {
                int t2 = 2 * h + tt;
                float4 xv = ldchunk(xs, j, t2);
                float4 fv = ldchunk(fo, j, t2);
                float4 gv = ldchunk(go, j, t2);
                float x[4] = {xv.x, xv.y, xv.z, xv.w};
                float f[4] = {fv.x, fv.y, fv.z, fv.w};
                float g[4] = {gv.x, gv.y, gv.z, gv.w};
                float o[4];
                #pragma unroll
                for (int q = 0; q < 4; ++q) {
                    int m = 4 * t2 + q;
                    o[q] = x[q] + (f[q] + g[q]) * scl[m];
                    ob[(size_t)(r0 + m) * ND + j] = o[q];
                }
                stchunk(xs, j, t2, make_float4(o[0], o[1], o[2], o[3]));
            }
        }
        __syncthreads();
    }
}

extern "C" void kernel_launch(void* const* d_in, const int* in_sizes, int n_in,
                              void* d_out, int out_size) {
    (void)in_sizes; (void)n_in; (void)out_size;
    const float* y0   = (const float*)d_in[0];
    const float* tv   = (const float*)d_in[1];
    const float* nz   = (const float*)d_in[2];
    const float* fw1  = (const float*)d_in[3];
    const float* fb1  = (const float*)d_in[4];
    const float* fw2  = (const float*)d_in[5];
    const float* fb2  = (const float*)d_in[6];
    const float* fw3  = (const float*)d_in[7];
    const float* fb3  = (const float*)d_in[8];
    const float* amw1 = (const float*)d_in[9];
    const float* amb1 = (const float*)d_in[10];
    const float* amw2 = (const float*)d_in[11];
    const float* amb2 = (const float*)d_in[12];
    const float* amw3 = (const float*)d_in[13];
    const float* amb3 = (const float*)d_in[14];
    const float* alw1 = (const float*)d_in[15];
    const float* alb1 = (const float*)d_in[16];
    const float* alw2 = (const float*)d_in[17];
    const float* alb2 = (const float*)d_in[18];
    const float* alw3 = (const float*)d_in[19];
    const float* alb3 = (const float*)d_in[20];
    const float* kw   = (const float*)d_in[21];
    float* out = (float*)d_out;

    const int shmem = 44288 * sizeof(float);  // 177,152 B
    cudaFuncSetAttribute(node_kernel, cudaFuncAttributeMaxDynamicSharedMemorySize, shmem);
    node_kernel<<<NBLOCKS, NTHR, shmem>>>(
        y0, tv, nz, fw1, fb1, fw2, fb2, fw3, fb3,
        amw1, amb1, amw2, amb2, amw3, amb3,
        alw1, alb1, alw2, alb2, alw3, alb3, kw, out);
}

// round 2
// speedup vs baseline: 1.0451x; 1.0451x over previous
#include <cuda_runtime.h>
#include <math.h>

#define BSZ 2048
#define ND 128
#define HID 256
#define SHD 64
#define NSTEPS 8
#define MROWS 16
#define NBLOCKS (BSZ / MROWS)
#define NTHR 512

typedef unsigned long long ull;

// ---------- packed f32x2 helpers ----------
__device__ __forceinline__ void fma2(ull &c, ull a, ull b) {
    asm("fma.rn.f32x2 %0, %1, %2, %3;" : "=l"(c) : "l"(a), "l"(b), "l"(c));
}
__device__ __forceinline__ ull packdup(float x) {
    ull r; asm("mov.b64 %0, {%1, %2};" : "=l"(r) : "f"(x), "f"(x)); return r;
}
__device__ __forceinline__ void unpack2(ull v, float &x, float &y) {
    asm("mov.b64 {%0, %1}, %2;" : "=f"(x), "=f"(y) : "l"(v));
}

// ---------- swizzled transposed [len][16] shared buffers ----------
__device__ __forceinline__ float4 ldchunk(const float* buf, int r, int t) {
    return reinterpret_cast<const float4*>(buf + r * 16)[t ^ ((r >> 1) & 3)];
}
__device__ __forceinline__ void stchunk(float* buf, int r, int t, float4 v) {
    reinterpret_cast<float4*>(buf + r * 16)[t ^ ((r >> 1) & 3)] = v;
}
__device__ __forceinline__ void load_row(const float* buf, int r, float v[16]) {
    #pragma unroll
    for (int t = 0; t < 4; ++t) {
        float4 c = ldchunk(buf, r, t);
        v[4*t+0] = c.x; v[4*t+1] = c.y; v[4*t+2] = c.z; v[4*t+3] = c.w;
    }
}
__device__ __forceinline__ void store_row(float* buf, int r, const float v[16]) {
    #pragma unroll
    for (int t = 0; t < 4; ++t)
        stchunk(buf, r, t, make_float4(v[4*t+0], v[4*t+1], v[4*t+2], v[4*t+3]));
}

__device__ __forceinline__ float softplus_f(float x) {
    return fmaxf(x, 0.f) + log1pf(expf(-fabsf(x)));
}
__device__ __forceinline__ float san(float x) { return isfinite(x) ? x : 0.f; }

// FMA 16 row-values of shared row k into 8 f32x2 accumulators
__device__ __forceinline__ void accum_rows(ull acc[8], const float* in_buf, int k, ull w2) {
    const ulonglong2* row = reinterpret_cast<const ulonglong2*>(in_buf + k * 16);
    int sw = (k >> 1) & 3;
    ulonglong2 p0 = row[0 ^ sw];
    ulonglong2 p1 = row[1 ^ sw];
    ulonglong2 p2 = row[2 ^ sw];
    ulonglong2 p3 = row[3 ^ sw];
    fma2(acc[0], p0.x, w2); fma2(acc[1], p0.y, w2);
    fma2(acc[2], p1.x, w2); fma2(acc[3], p1.y, w2);
    fma2(acc[4], p2.x, w2); fma2(acc[5], p2.y, w2);
    fma2(acc[6], p3.x, w2); fma2(acc[7], p3.y, w2);
}

// GEMM partial: v[16] = sum_{k0..k0+KS} in[k][m] * W[k][j]  (W global, row stride ldw)
__device__ __forceinline__ void gaccum(float v[16], const float* in_buf,
                                       const float* __restrict__ W, int ldw,
                                       int j, int k0, int KS) {
    ull acc[8];
    #pragma unroll
    for (int p = 0; p < 8; ++p) acc[p] = 0ULL;
    const float* __restrict__ wp = W + (size_t)k0 * ldw + j;
    #pragma unroll 4
    for (int kk = 0; kk < KS; ++kk) {
        float w = *wp; wp += ldw;
        accum_rows(acc, in_buf, k0 + kk, packdup(w));
    }
    #pragma unroll
    for (int p = 0; p < 8; ++p) unpack2(acc[p], v[2*p], v[2*p+1]);
}

// Jacobian GEMM partial: weights kw^T from shared (padded 129)
__device__ __forceinline__ void jaccum(float v[16], const float* ub,
                                       const float* kwt, int j, int i0) {
    ull acc[8];
    #pragma unroll
    for (int p = 0; p < 8; ++p) acc[p] = 0ULL;
    const float* wp = kwt + j * 129 + i0;
    #pragma unroll 4
    for (int ii = 0; ii < 64; ++ii) {
        float w = wp[ii];
        accum_rows(acc, ub, i0 + ii, packdup(w));
    }
    #pragma unroll
    for (int p = 0; p < 8; ++p) unpack2(acc[p], v[2*p], v[2*p+1]);
}

// warp-level reduce of 16 per-row partials; lane0 holds sums
__device__ __forceinline__ void warp_reduce16(float sq[16]) {
    #pragma unroll
    for (int off = 16; off > 0; off >>= 1) {
        #pragma unroll
        for (int m = 0; m < 16; ++m)
            sq[m] += __shfl_down_sync(0xffffffffu, sq[m], off);
    }
}

__global__ void __launch_bounds__(NTHR, 1)
node_kernel(const float* __restrict__ y0, const float* __restrict__ tv,
            const float* __restrict__ noise,
            const float* __restrict__ fw1, const float* __restrict__ fb1,
            const float* __restrict__ fw2, const float* __restrict__ fb2,
            const float* __restrict__ fw3, const float* __restrict__ fb3,
            const float* __restrict__ amw1, const float* __restrict__ amb1,
            const float* __restrict__ amw2, const float* __restrict__ amb2,
            const float* __restrict__ amw3, const float* __restrict__ amb3,
            const float* __restrict__ alw1, const float* __restrict__ alb1,
            const float* __restrict__ alw2, const float* __restrict__ alb2,
            const float* __restrict__ alw3, const float* __restrict__ alb3,
            const float* __restrict__ kw, float* __restrict__ out)
{
    extern __shared__ float smem[];
    float* kwt  = smem;              // 16512
    float* xs   = kwt + 16512;       // 2048
    float* h1   = xs + 2048;         // 4096
    float* h2   = h1 + 4096;         // 4096
    float* fo   = h2 + 4096;         // 2048
    float* ko   = fo + 2048;         // 2048
    float* mo   = ko + 2048;         // 2048
    float* lso  = mo + 2048;         // 2048
    float* go   = lso + 2048;        // 2048  (stores f+g)
    float* ubf  = go + 2048;         // 2048
    float* ubg  = ubf + 2048;        // 2048
    float* a1m  = ubg + 2048;        // 1024
    float* a1l  = a1m + 1024;        // 1024
    float* a2m  = a1l + 1024;        // 1024
    float* a2l  = a2m + 1024;        // 1024
    float* cb   = a2l + 1024;        // 4096 (256 rows)
    float* redk = cb + 4096;         // 64
    float* redf = redk + 64;         // 64
    float* redg = redf + 64;         // 64
    float* kn2s = redg + 64;         // 16

    const int tid = threadIdx.x;
    const int r0 = blockIdx.x * MROWS;
    const float dt = tv[1] - tv[0];
    const int ewj = tid & 127;       // elementwise mapping: col j
    const int ewt = tid >> 7;        // elementwise mapping: chunk t (0..3)

    // stage kw^T into padded shared
    for (int idx = tid; idx < ND * ND; idx += NTHR) {
        int i = idx >> 7, jj = idx & 127;
        kwt[jj * 129 + i] = kw[idx];
    }
    // load y0 tile (transposed+swizzled); emit output step 0
    {
        float a[4];
        #pragma unroll
        for (int q = 0; q < 4; ++q) {
            int m = 4 * ewt + q;
            float val = y0[(size_t)(r0 + m) * ND + ewj];
            out[(size_t)(r0 + m) * ND + ewj] = val;
            a[q] = val;
        }
        stchunk(xs, ewj, ewt, make_float4(a[0], a[1], a[2], a[3]));
    }
    __syncthreads();

    for (int step = 0; step < NSTEPS; ++step) {
        float v[16];
        // ======== Stage A: f1 || k || am1 || al1  (perfect 512-col packing) ========
        if (tid < 256) {                       // f1: tanh(x @ fw1 + fb1) -> h1
            gaccum(v, xs, fw1, HID, tid, 0, ND);
            float b = fb1[tid];
            #pragma unroll
            for (int m = 0; m < 16; ++m) v[m] = tanhf(v[m] + b);
            store_row(h1, tid, v);
        } else if (tid < 384) {                // k: tanh(x @ kw) -> ko, + ||k||^2 partials
            int j = tid - 256;
            gaccum(v, xs, kw, ND, j, 0, ND);
            float sq[16];
            #pragma unroll
            for (int m = 0; m < 16; ++m) { v[m] = tanhf(v[m]); sq[m] = v[m] * v[m]; }
            store_row(ko, j, v);
            warp_reduce16(sq);
            if ((tid & 31) == 0) {
                int w = (tid - 256) >> 5;
                #pragma unroll
                for (int m = 0; m < 16; ++m) redk[w * 16 + m] = sq[m];
            }
        } else if (tid < 448) {                // am1: relu -> a1m
            int j = tid - 384;
            gaccum(v, xs, amw1, SHD, j, 0, ND);
            float b = amb1[j];
            #pragma unroll
            for (int m = 0; m < 16; ++m) v[m] = fmaxf(v[m] + b, 0.f);
            store_row(a1m, j, v);
        } else {                               // al1: relu -> a1l
            int j = tid - 448;
            gaccum(v, xs, alw1, SHD, j, 0, ND);
            float b = alb1[j];
            #pragma unroll
            for (int m = 0; m < 16; ++m) v[m] = fmaxf(v[m] + b, 0.f);
            store_row(a1l, j, v);
        }
        __syncthreads();

        // ======== Stage B: f2 (S=2 over all 512) ========
        {
            int j = tid & 255, s = tid >> 8;
            gaccum(v, h1, fw2, HID, j, s * 128, 128);
            if (s == 1) store_row(cb, j, v);
        }
        __syncthreads();
        if (tid < 256) {                       // combine + softplus -> h2
            float w16[16];
            load_row(cb, tid, w16);
            float b = fb2[tid];
            #pragma unroll
            for (int m = 0; m < 16; ++m) v[m] = softplus_f(v[m] + w16[m] + b);
            store_row(h2, tid, v);
        }
        if (tid < 16)                          // finish ||k||^2
            kn2s[tid] = redk[tid] + redk[16 + tid] + redk[32 + tid] + redk[48 + tid];
        __syncthreads();

        // ======== Stage C p1: f3 (S=2, 256 thr) || am2 || al2 ========
        if (tid < 256) {
            int j = tid & 127, s = tid >> 7;
            gaccum(v, h2, fw3, ND, j, s * 128, 128);
            if (s == 1) store_row(cb, j, v);
        } else if (tid < 320) {                // am2: relu -> a2m
            int j = tid - 256;
            gaccum(v, a1m, amw2, SHD, j, 0, SHD);
            float b = amb2[j];
            #pragma unroll
            for (int m = 0; m < 16; ++m) v[m] = fmaxf(v[m] + b, 0.f);
            store_row(a2m, j, v);
        } else if (tid < 384) {                // al2: relu -> a2l
            int j = tid - 320;
            gaccum(v, a1l, alw2, SHD, j, 0, SHD);
            float b = alb2[j];
            #pragma unroll
            for (int m = 0; m < 16; ++m) v[m] = fmaxf(v[m] + b, 0.f);
            store_row(a2l, j, v);
        }
        __syncthreads();

        // ======== Stage C p2: f3 combine || am3 || al3 ========
        if (tid < 128) {                       // fo = f3 (no act)
            float w16[16];
            load_row(cb, tid, w16);
            float b = fb3[tid];
            #pragma unroll
            for (int m = 0; m < 16; ++m) v[m] = v[m] + w16[m] + b;
            store_row(fo, tid, v);
        } else if (tid < 256) {                // am3: tanh -> mo
            int j = tid - 128;
            gaccum(v, a2m, amw3, ND, j, 0, SHD);
            float b = amb3[j];
            #pragma unroll
            for (int m = 0; m < 16; ++m) v[m] = tanhf(v[m] + b);
            store_row(mo, j, v);
        } else if (tid < 384) {                // al3: linear -> lso
            int j = tid - 256;
            gaccum(v, a2l, alw3, ND, j, 0, SHD);
            float b = alb3[j];
            #pragma unroll
            for (int m = 0; m < 16; ++m) v[m] = v[m] + b;
            store_row(lso, j, v);
        }
        __syncthreads();

        // ======== Stage E: g, f+g, u_f, u_g (elementwise) ========
        {
            float4 kv = ldchunk(ko, ewj, ewt);
            float4 fv = ldchunk(fo, ewj, ewt);
            float4 mv = ldchunk(mo, ewj, ewt);
            float4 lv = ldchunk(lso, ewj, ewt);
            float kk[4] = {kv.x, kv.y, kv.z, kv.w};
            float ff[4] = {fv.x, fv.y, fv.z, fv.w};
            float mm[4] = {mv.x, mv.y, mv.z, mv.w};
            float ll[4] = {lv.x, lv.y, lv.z, lv.w};
            const float* np = noise + (size_t)step * BSZ * ND + (size_t)(r0 + 4 * ewt) * ND + ewj;
            float gs[4], uf[4], ug[4];
            #pragma unroll
            for (int q = 0; q < 4; ++q) {
                float sd = softplus_f(san(ll[q]));
                float e = np[(size_t)q * ND];
                float g = tanhf(san(mm[q]) + sd * e);
                float om = 1.f - kk[q] * kk[q];
                gs[q] = ff[q] + g;
                uf[q] = om * ff[q];
                ug[q] = om * g;
            }
            stchunk(go, ewj, ewt, make_float4(gs[0], gs[1], gs[2], gs[3]));
            stchunk(ubf, ewj, ewt, make_float4(uf[0], uf[1], uf[2], uf[3]));
            stchunk(ubg, ewj, ewt, make_float4(ug[0], ug[1], ug[2], ug[3]));
        }
        __syncthreads();

        // ======== Stage F p1: jacf (256 thr) || jacg (256 thr) ========
        if (tid < 256) {
            int j = tid & 127, s = tid >> 7;
            jaccum(v, ubf, kwt, j, s * 64);
            if (s == 1) store_row(cb, j, v);
        } else {
            int jt = tid - 256;
            int j = jt & 127, s = jt >> 7;
            jaccum(v, ubg, kwt, j, s * 64);
            if (s == 1) store_row(cb, 128 + j, v);
        }
        __syncthreads();

        // ======== Stage F p2: combine + reduce -> redf / redg ========
        if (tid < 128) {                       // ||Jf||^2 partials
            float w16[16];
            load_row(cb, tid, w16);
            float sq[16];
            #pragma unroll
            for (int m = 0; m < 16; ++m) { float x = v[m] + w16[m]; sq[m] = x * x; }
            warp_reduce16(sq);
            if ((tid & 31) == 0) {
                int w = tid >> 5;
                #pragma unroll
                for (int m = 0; m < 16; ++m) redf[w * 16 + m] = sq[m];
            }
        } else if (tid >= 256 && tid < 384) {  // k . Jg partials
            int j = tid - 256;
            float w16[16], kr[16];
            load_row(cb, 128 + j, w16);
            load_row(ko, j, kr);
            float sq[16];
            #pragma unroll
            for (int m = 0; m < 16; ++m) sq[m] = (v[m] + w16[m]) * kr[m];
            warp_reduce16(sq);
            if ((tid & 31) == 0) {
                int w = (tid - 256) >> 5;
                #pragma unroll
                for (int m = 0; m < 16; ++m) redg[w * 16 + m] = sq[m];
            }
        }
        __syncthreads();

        // ======== Stage F p3: inline mask + Euler update + output ========
        {
            float sclq[4];
            #pragma unroll
            for (int q = 0; q < 4; ++q) {
                int m = 4 * ewt + q;
                float kn2 = kn2s[m];
                float jf2 = redf[m] + redf[16 + m] + redf[32 + m] + redf[48 + m];
                float c2v = redg[m] + redg[16 + m] + redg[32 + m] + redg[48 + m];
                float kn = sqrtf(kn2);
                float kn9 = kn2 * kn2 * kn2 * kn2 * kn;
                float c1 = sqrtf(jf2) - 60.0f * kn9;
                float c2 = c2v - 20.0f * kn9 * kn;
                bool mask = (c1 > 1e-8f) || (c2 < -1e-8f);
                sclq[q] = mask ? (0.5f * dt) : dt;
            }
            float4 xv = ldchunk(xs, ewj, ewt);
            float4 dv = ldchunk(go, ewj, ewt);
            float x[4] = {xv.x, xv.y, xv.z, xv.w};
            float d[4] = {dv.x, dv.y, dv.z, dv.w};
            float o[4];
            float* ob = out + (size_t)(step + 1) * BSZ * ND;
            #pragma unroll
            for (int q = 0; q < 4; ++q) {
                int m = 4 * ewt + q;
                o[q] = x[q] + d[q] * sclq[q];
                ob[(size_t)(r0 + m) * ND + ewj] = o[q];
            }
            stchunk(xs, ewj, ewt, make_float4(o[0], o[1], o[2], o[3]));
        }
        __syncthreads();
    }
}

extern "C" void kernel_launch(void* const* d_in, const int* in_sizes, int n_in,
                              void* d_out, int out_size) {
    (void)in_sizes; (void)n_in; (void)out_size;
    const float* y0   = (const float*)d_in[0];
    const float* tv   = (const float*)d_in[1];
    const float* nz   = (const float*)d_in[2];
    const float* fw1  = (const float*)d_in[3];
    const float* fb1  = (const float*)d_in[4];
    const float* fw2  = (const float*)d_in[5];
    const float* fb2  = (const float*)d_in[6];
    const float* fw3  = (const float*)d_in[7];
    const float* fb3  = (const float*)d_in[8];
    const float* amw1 = (const float*)d_in[9];
    const float* amb1 = (const float*)d_in[10];
    const float* amw2 = (const float*)d_in[11];
    const float* amb2 = (const float*)d_in[12];
    const float* amw3 = (const float*)d_in[13];
    const float* amb3 = (const float*)d_in[14];
    const float* alw1 = (const float*)d_in[15];
    const float* alb1 = (const float*)d_in[16];
    const float* alw2 = (const float*)d_in[17];
    const float* alb2 = (const float*)d_in[18];
    const float* alw3 = (const float*)d_in[19];
    const float* alb3 = (const float*)d_in[20];
    const float* kw   = (const float*)d_in[21];
    float* out = (float*)d_out;

    const int shmem = 49488 * sizeof(float);  // 197,952 B
    cudaFuncSetAttribute(node_kernel, cudaFuncAttributeMaxDynamicSharedMemorySize, shmem);
    node_kernel<<<NBLOCKS, NTHR, shmem>>>(
        y0, tv, nz, fw1, fb1, fw2, fb2, fw3, fb3,
        amw1, amb1, amw2, amb2, amw3, amb3,
        alw1, alb1, alw2, alb2, alw3, alb3, kw, out);
}

// round 3
// speedup vs baseline: 1.1327x; 1.0837x over previous
#include <cuda_runtime.h>
#include <math.h>

#define BSZ 2048
#define ND 128
#define HID 256
#define SHD 64
#define NSTEPS 8
#define MROWS 16
#define NBLOCKS (BSZ / MROWS)
#define NTHR 512

typedef unsigned long long ull;

// ---------- packed f32x2 helpers ----------
__device__ __forceinline__ void fma2(ull &c, ull a, ull b) {
    asm("fma.rn.f32x2 %0, %1, %2, %3;" : "=l"(c) : "l"(a), "l"(b), "l"(c));
}
__device__ __forceinline__ ull packdup(float x) {
    ull r; asm("mov.b64 %0, {%1, %2};" : "=l"(r) : "f"(x), "f"(x)); return r;
}
__device__ __forceinline__ void unpack2(ull v, float &x, float &y) {
    asm("mov.b64 {%0, %1}, %2;" : "=f"(x), "=f"(y) : "l"(v));
}

// ---------- swizzled transposed [len][16] shared buffers ----------
__device__ __forceinline__ float4 ldchunk(const float* buf, int r, int t) {
    return reinterpret_cast<const float4*>(buf + r * 16)[t ^ ((r >> 1) & 3)];
}
__device__ __forceinline__ void stchunk(float* buf, int r, int t, float4 v) {
    reinterpret_cast<float4*>(buf + r * 16)[t ^ ((r >> 1) & 3)] = v;
}
__device__ __forceinline__ void load_row(const float* buf, int r, float v[16]) {
    #pragma unroll
    for (int t = 0; t < 4; ++t) {
        float4 c = ldchunk(buf, r, t);
        v[4*t+0] = c.x; v[4*t+1] = c.y; v[4*t+2] = c.z; v[4*t+3] = c.w;
    }
}
__device__ __forceinline__ void store_row(float* buf, int r, const float v[16]) {
    #pragma unroll
    for (int t = 0; t < 4; ++t)
        stchunk(buf, r, t, make_float4(v[4*t+0], v[4*t+1], v[4*t+2], v[4*t+3]));
}

__device__ __forceinline__ float softplus_f(float x) {
    return fmaxf(x, 0.f) + log1pf(expf(-fabsf(x)));
}
__device__ __forceinline__ float san(float x) { return isfinite(x) ? x : 0.f; }

// FMA 16 row-values of shared row k into 8 f32x2 accumulators
__device__ __forceinline__ void accum_rows(ull acc[8], const float* in_buf, int k, ull w2) {
    const ulonglong2* row = reinterpret_cast<const ulonglong2*>(in_buf + k * 16);
    int sw = (k >> 1) & 3;
    ulonglong2 p0 = row[0 ^ sw];
    ulonglong2 p1 = row[1 ^ sw];
    ulonglong2 p2 = row[2 ^ sw];
    ulonglong2 p3 = row[3 ^ sw];
    fma2(acc[0], p0.x, w2); fma2(acc[1], p0.y, w2);
    fma2(acc[2], p1.x, w2); fma2(acc[3], p1.y, w2);
    fma2(acc[4], p2.x, w2); fma2(acc[5], p2.y, w2);
    fma2(acc[6], p3.x, w2); fma2(acc[7], p3.y, w2);
}

// GEMM partial with explicit 8-deep weight prefetch (8 LDGs in flight).
// v[16] = sum_{k0..k0+KS} in[k][m] * W[k][j].  KS must be a multiple of 8, >= 16.
__device__ __forceinline__ void gaccum(float v[16], const float* in_buf,
                                       const float* __restrict__ W, int ldw,
                                       int j, int k0, int KS) {
    ull acc[8];
    #pragma unroll
    for (int p = 0; p < 8; ++p) acc[p] = 0ULL;
    const float* __restrict__ wp = W + (size_t)k0 * ldw + j;
    float w[8];
    #pragma unroll
    for (int u = 0; u < 8; ++u) w[u] = wp[(size_t)u * ldw];
    wp += (size_t)8 * ldw;
    for (int kk = 0; kk < KS - 8; kk += 8) {
        float wn[8];
        #pragma unroll
        for (int u = 0; u < 8; ++u) wn[u] = wp[(size_t)u * ldw];
        wp += (size_t)8 * ldw;
        #pragma unroll
        for (int u = 0; u < 8; ++u) accum_rows(acc, in_buf, k0 + kk + u, packdup(w[u]));
        #pragma unroll
        for (int u = 0; u < 8; ++u) w[u] = wn[u];
    }
    #pragma unroll
    for (int u = 0; u < 8; ++u) accum_rows(acc, in_buf, k0 + KS - 8 + u, packdup(w[u]));
    #pragma unroll
    for (int p = 0; p < 8; ++p) unpack2(acc[p], v[2*p], v[2*p+1]);
}

// Jacobian GEMM partial: weights kw^T from shared (padded 129); 64 iters
__device__ __forceinline__ void jaccum(float v[16], const float* ub,
                                       const float* kwt, int j, int i0) {
    ull acc[8];
    #pragma unroll
    for (int p = 0; p < 8; ++p) acc[p] = 0ULL;
    const float* wp = kwt + j * 129 + i0;
    #pragma unroll 8
    for (int ii = 0; ii < 64; ++ii) {
        float w = wp[ii];
        accum_rows(acc, ub, i0 + ii, packdup(w));
    }
    #pragma unroll
    for (int p = 0; p < 8; ++p) unpack2(acc[p], v[2*p], v[2*p+1]);
}

// warp-level reduce of 16 per-row partials; lane0 holds sums
__device__ __forceinline__ void warp_reduce16(float sq[16]) {
    #pragma unroll
    for (int off = 16; off > 0; off >>= 1) {
        #pragma unroll
        for (int m = 0; m < 16; ++m)
            sq[m] += __shfl_down_sync(0xffffffffu, sq[m], off);
    }
}

__global__ void __launch_bounds__(NTHR, 1)
node_kernel(const float* __restrict__ y0, const float* __restrict__ tv,
            const float* __restrict__ noise,
            const float* __restrict__ fw1, const float* __restrict__ fb1,
            const float* __restrict__ fw2, const float* __restrict__ fb2,
            const float* __restrict__ fw3, const float* __restrict__ fb3,
            const float* __restrict__ amw1, const float* __restrict__ amb1,
            const float* __restrict__ amw2, const float* __restrict__ amb2,
            const float* __restrict__ amw3, const float* __restrict__ amb3,
            const float* __restrict__ alw1, const float* __restrict__ alb1,
            const float* __restrict__ alw2, const float* __restrict__ alb2,
            const float* __restrict__ alw3, const float* __restrict__ alb3,
            const float* __restrict__ kw, float* __restrict__ out)
{
    extern __shared__ float smem[];
    float* kwt  = smem;              // 16512
    float* xs   = kwt + 16512;       // 2048
    float* h1   = xs + 2048;         // 4096
    float* h2   = h1 + 4096;         // 4096
    float* fo   = h2 + 4096;         // 2048
    float* ko   = fo + 2048;         // 2048
    float* mo   = ko + 2048;         // 2048
    float* lso  = mo + 2048;         // 2048
    float* go   = lso + 2048;        // 2048  (stores f+g)
    float* ubf  = go + 2048;         // 2048
    float* ubg  = ubf + 2048;        // 2048
    float* a1m  = ubg + 2048;        // 1024
    float* a1l  = a1m + 1024;        // 1024
    float* a2m  = a1l + 1024;        // 1024
    float* a2l  = a2m + 1024;        // 1024
    float* cb   = a2l + 1024;        // 4096 (256 rows)
    float* redk = cb + 4096;         // 64
    float* redf = redk + 64;         // 64
    float* redg = redf + 64;         // 64
    float* kn2s = redg + 64;         // 16

    const int tid = threadIdx.x;
    const int r0 = blockIdx.x * MROWS;
    const float dt = tv[1] - tv[0];
    const int ewj = tid & 127;       // elementwise mapping: col j
    const int ewt = tid >> 7;        // elementwise mapping: chunk t (0..3)

    // stage kw^T into padded shared
    for (int idx = tid; idx < ND * ND; idx += NTHR) {
        int i = idx >> 7, jj = idx & 127;
        kwt[jj * 129 + i] = kw[idx];
    }
    // load y0 tile (transposed+swizzled); emit output step 0
    {
        float a[4];
        #pragma unroll
        for (int q = 0; q < 4; ++q) {
            int m = 4 * ewt + q;
            float val = y0[(size_t)(r0 + m) * ND + ewj];
            out[(size_t)(r0 + m) * ND + ewj] = val;
            a[q] = val;
        }
        stchunk(xs, ewj, ewt, make_float4(a[0], a[1], a[2], a[3]));
    }
    __syncthreads();

    for (int step = 0; step < NSTEPS; ++step) {
        float v[16];
        // noise prefetch for this step (consumed in stage E, ~thousands of cycles later)
        float nse[4];
        {
            const float* np = noise + (size_t)step * BSZ * ND + (size_t)(r0 + 4 * ewt) * ND + ewj;
            #pragma unroll
            for (int q = 0; q < 4; ++q) nse[q] = np[(size_t)q * ND];
        }

        // ======== Stage A: f1 || k || am1 || al1  (perfect 512-col packing) ========
        if (tid < 256) {                       // f1: tanh(x @ fw1 + fb1) -> h1
            gaccum(v, xs, fw1, HID, tid, 0, ND);
            float b = fb1[tid];
            #pragma unroll
            for (int m = 0; m < 16; ++m) v[m] = tanhf(v[m] + b);
            store_row(h1, tid, v);
        } else if (tid < 384) {                // k: tanh(x @ kw) -> ko, + ||k||^2 partials
            int j = tid - 256;
            gaccum(v, xs, kw, ND, j, 0, ND);
            float sq[16];
            #pragma unroll
            for (int m = 0; m < 16; ++m) { v[m] = tanhf(v[m]); sq[m] = v[m] * v[m]; }
            store_row(ko, j, v);
            warp_reduce16(sq);
            if ((tid & 31) == 0) {
                int w = (tid - 256) >> 5;
                #pragma unroll
                for (int m = 0; m < 16; ++m) redk[w * 16 + m] = sq[m];
            }
        } else if (tid < 448) {                // am1: relu -> a1m
            int j = tid - 384;
            gaccum(v, xs, amw1, SHD, j, 0, ND);
            float b = amb1[j];
            #pragma unroll
            for (int m = 0; m < 16; ++m) v[m] = fmaxf(v[m] + b, 0.f);
            store_row(a1m, j, v);
        } else {                               // al1: relu -> a1l
            int j = tid - 448;
            gaccum(v, xs, alw1, SHD, j, 0, ND);
            float b = alb1[j];
            #pragma unroll
            for (int m = 0; m < 16; ++m) v[m] = fmaxf(v[m] + b, 0.f);
            store_row(a1l, j, v);
        }
        __syncthreads();

        // ======== Stage B: f2 (S=2 over all 512) ========
        {
            int j = tid & 255, s = tid >> 8;
            gaccum(v, h1, fw2, HID, j, s * 128, 128);
            if (s == 1) store_row(cb, j, v);
        }
        __syncthreads();
        if (tid < 256) {                       // combine + softplus -> h2
            float w16[16];
            load_row(cb, tid, w16);
            float b = fb2[tid];
            #pragma unroll
            for (int m = 0; m < 16; ++m) v[m] = softplus_f(v[m] + w16[m] + b);
            store_row(h2, tid, v);
        }
        if (tid < 16)                          // finish ||k||^2
            kn2s[tid] = redk[tid] + redk[16 + tid] + redk[32 + tid] + redk[48 + tid];
        __syncthreads();

        // ======== Stage C p1: f3 (S=2, 256 thr) || am2 || al2 ========
        if (tid < 256) {
            int j = tid & 127, s = tid >> 7;
            gaccum(v, h2, fw3, ND, j, s * 128, 128);
            if (s == 1) store_row(cb, j, v);
        } else if (tid < 320) {                // am2: relu -> a2m
            int j = tid - 256;
            gaccum(v, a1m, amw2, SHD, j, 0, SHD);
            float b = amb2[j];
            #pragma unroll
            for (int m = 0; m < 16; ++m) v[m] = fmaxf(v[m] + b, 0.f);
            store_row(a2m, j, v);
        } else if (tid < 384) {                // al2: relu -> a2l
            int j = tid - 320;
            gaccum(v, a1l, alw2, SHD, j, 0, SHD);
            float b = alb2[j];
            #pragma unroll
            for (int m = 0; m < 16; ++m) v[m] = fmaxf(v[m] + b, 0.f);
            store_row(a2l, j, v);
        }
        __syncthreads();

        // ======== Stage C p2: f3 combine || am3 || al3 ========
        if (tid < 128) {                       // fo = f3 (no act)
            float w16[16];
            load_row(cb, tid, w16);
            float b = fb3[tid];
            #pragma unroll
            for (int m = 0; m < 16; ++m) v[m] = v[m] + w16[m] + b;
            store_row(fo, tid, v);
        } else if (tid < 256) {                // am3: tanh -> mo
            int j = tid - 128;
            gaccum(v, a2m, amw3, ND, j, 0, SHD);
            float b = amb3[j];
            #pragma unroll
            for (int m = 0; m < 16; ++m) v[m] = tanhf(v[m] + b);
            store_row(mo, j, v);
        } else if (tid < 384) {                // al3: linear -> lso
            int j = tid - 256;
            gaccum(v, a2l, alw3, ND, j, 0, SHD);
            float b = alb3[j];
            #pragma unroll
            for (int m = 0; m < 16; ++m) v[m] = v[m] + b;
            store_row(lso, j, v);
        }
        __syncthreads();

        // ======== Stage E: g, f+g, u_f, u_g (elementwise) ========
        {
            float4 kv = ldchunk(ko, ewj, ewt);
            float4 fv = ldchunk(fo, ewj, ewt);
            float4 mv = ldchunk(mo, ewj, ewt);
            float4 lv = ldchunk(lso, ewj, ewt);
            float kk[4] = {kv.x, kv.y, kv.z, kv.w};
            float ff[4] = {fv.x, fv.y, fv.z, fv.w};
            float mm[4] = {mv.x, mv.y, mv.z, mv.w};
            float ll[4] = {lv.x, lv.y, lv.z, lv.w};
            float gs[4], uf[4], ug[4];
            #pragma unroll
            for (int q = 0; q < 4; ++q) {
                float sd = softplus_f(san(ll[q]));
                float g = tanhf(san(mm[q]) + sd * nse[q]);
                float om = 1.f - kk[q] * kk[q];
                gs[q] = ff[q] + g;
                uf[q] = om * ff[q];
                ug[q] = om * g;
            }
            stchunk(go, ewj, ewt, make_float4(gs[0], gs[1], gs[2], gs[3]));
            stchunk(ubf, ewj, ewt, make_float4(uf[0], uf[1], uf[2], uf[3]));
            stchunk(ubg, ewj, ewt, make_float4(ug[0], ug[1], ug[2], ug[3]));
        }
        __syncthreads();

        // ======== Stage F p1: jacf (256 thr) || jacg (256 thr) ========
        if (tid < 256) {
            int j = tid & 127, s = tid >> 7;
            jaccum(v, ubf, kwt, j, s * 64);
            if (s == 1) store_row(cb, j, v);
        } else {
            int jt = tid - 256;
            int j = jt & 127, s = jt >> 7;
            jaccum(v, ubg, kwt, j, s * 64);
            if (s == 1) store_row(cb, 128 + j, v);
        }
        __syncthreads();

        // ======== Stage F p2: combine + reduce -> redf / redg ========
        if (tid < 128) {                       // ||Jf||^2 partials
            float w16[16];
            load_row(cb, tid, w16);
            float sq[16];
            #pragma unroll
            for (int m = 0; m < 16; ++m) { float x = v[m] + w16[m]; sq[m] = x * x; }
            warp_reduce16(sq);
            if ((tid & 31) == 0) {
                int w = tid >> 5;
                #pragma unroll
                for (int m = 0; m < 16; ++m) redf[w * 16 + m] = sq[m];
            }
        } else if (tid >= 256 && tid < 384) {  // k . Jg partials
            int j = tid - 256;
            float w16[16], kr[16];
            load_row(cb, 128 + j, w16);
            load_row(ko, j, kr);
            float sq[16];
            #pragma unroll
            for (int m = 0; m < 16; ++m) sq[m] = (v[m] + w16[m]) * kr[m];
            warp_reduce16(sq);
            if ((tid & 31) == 0) {
                int w = (tid - 256) >> 5;
                #pragma unroll
                for (int m = 0; m < 16; ++m) redg[w * 16 + m] = sq[m];
            }
        }
        __syncthreads();

        // ======== Stage F p3: inline mask + Euler update + output ========
        {
            float sclq[4];
            #pragma unroll
            for (int q = 0; q < 4; ++q) {
                int m = 4 * ewt + q;
                float kn2 = kn2s[m];
                float jf2 = redf[m] + redf[16 + m] + redf[32 + m] + redf[48 + m];
                float c2v = redg[m] + redg[16 + m] + redg[32 + m] + redg[48 + m];
                float kn = sqrtf(kn2);
                float kn9 = kn2 * kn2 * kn2 * kn2 * kn;
                float c1 = sqrtf(jf2) - 60.0f * kn9;
                float c2 = c2v - 20.0f * kn9 * kn;
                bool mask = (c1 > 1e-8f) || (c2 < -1e-8f);
                sclq[q] = mask ? (0.5f * dt) : dt;
            }
            float4 xv = ldchunk(xs, ewj, ewt);
            float4 dv = ldchunk(go, ewj, ewt);
            float x[4] = {xv.x, xv.y, xv.z, xv.w};
            float d[4] = {dv.x, dv.y, dv.z, dv.w};
            float o[4];
            float* ob = out + (size_t)(step + 1) * BSZ * ND;
            #pragma unroll
            for (int q = 0; q < 4; ++q) {
                int m = 4 * ewt + q;
                o[q] = x[q] + d[q] * sclq[q];
                ob[(size_t)(r0 + m) * ND + ewj] = o[q];
            }
            stchunk(xs, ewj, ewt, make_float4(o[0], o[1], o[2], o[3]));
        }
        __syncthreads();
    }
}

extern "C" void kernel_launch(void* const* d_in, const int* in_sizes, int n_in,
                              void* d_out, int out_size) {
    (void)in_sizes; (void)n_in; (void)out_size;
    const float* y0   = (const float*)d_in[0];
    const float* tv   = (const float*)d_in[1];
    const float* nz   = (const float*)d_in[2];
    const float* fw1  = (const float*)d_in[3];
    const float* fb1  = (const float*)d_in[4];
    const float* fw2  = (const float*)d_in[5];
    const float* fb2  = (const float*)d_in[6];
    const float* fw3  = (const float*)d_in[7];
    const float* fb3  = (const float*)d_in[8];
    const float* amw1 = (const float*)d_in[9];
    const float* amb1 = (const float*)d_in[10];
    const float* amw2 = (const float*)d_in[11];
    const float* amb2 = (const float*)d_in[12];
    const float* amw3 = (const float*)d_in[13];
    const float* amb3 = (const float*)d_in[14];
    const float* alw1 = (const float*)d_in[15];
    const float* alb1 = (const float*)d_in[16];
    const float* alw2 = (const float*)d_in[17];
    const float* alb2 = (const float*)d_in[18];
    const float* alw3 = (const float*)d_in[19];
    const float* alb3 = (const float*)d_in[20];
    const float* kw   = (const float*)d_in[21];
    float* out = (float*)d_out;

    const int shmem = 49488 * sizeof(float);  // 197,952 B
    cudaFuncSetAttribute(node_kernel, cudaFuncAttributeMaxDynamicSharedMemorySize, shmem);
    node_kernel<<<NBLOCKS, NTHR, shmem>>>(
        y0, tv, nz, fw1, fb1, fw2, fb2, fw3, fb3,
        amw1, amb1, amw2, amb2, amw3, amb3,
        alw1, alb1, alw2, alb2, alw3, alb3, kw, out);
}

// round 5
// speedup vs baseline: 1.2545x; 1.1076x over previous
#include <cuda_runtime.h>
#include <math.h>

#define BSZ 2048
#define ND 128
#define HID 256
#define SHD 64
#define NSTEPS 8
#define MROWS 8
#define NBLOCKS (BSZ / MROWS)
#define NTHR 256

typedef unsigned long long ull;

// ---------- packed f32x2 helpers ----------
__device__ __forceinline__ void fma2(ull &c, ull a, ull b) {
    asm("fma.rn.f32x2 %0, %1, %2, %3;" : "=l"(c) : "l"(a), "l"(b), "l"(c));
}
__device__ __forceinline__ ull packdup(float x) {
    ull r; asm("mov.b64 %0, {%1, %2};" : "=l"(r) : "f"(x), "f"(x)); return r;
}
__device__ __forceinline__ void unpack2(ull v, float &x, float &y) {
    asm("mov.b64 {%0, %1}, %2;" : "=f"(x), "=f"(y) : "l"(v));
}

// ---------- transposed [len][8] shared rows (reads are row-broadcast) ----------
__device__ __forceinline__ void load_row8(const float* buf, int r, float v[8]) {
    const float4* p = reinterpret_cast<const float4*>(buf + r * 8);
    float4 c0 = p[0], c1 = p[1];
    v[0]=c0.x; v[1]=c0.y; v[2]=c0.z; v[3]=c0.w;
    v[4]=c1.x; v[5]=c1.y; v[6]=c1.z; v[7]=c1.w;
}
__device__ __forceinline__ void store_row8(float* buf, int r, const float v[8]) {
    float4* p = reinterpret_cast<float4*>(buf + r * 8);
    p[0] = make_float4(v[0], v[1], v[2], v[3]);
    p[1] = make_float4(v[4], v[5], v[6], v[7]);
}

__device__ __forceinline__ float softplus_f(float x) {
    return fmaxf(x, 0.f) + log1pf(expf(-fabsf(x)));
}
__device__ __forceinline__ float san(float x) { return isfinite(x) ? x : 0.f; }

// FMA one shared row (8 values) into accumulators; 2-col and 1-col variants
__device__ __forceinline__ void accum2(ull a0[4], ull a1[4], const float* in_buf,
                                       int k, ull w0, ull w1) {
    const ulonglong2* row = reinterpret_cast<const ulonglong2*>(in_buf + k * 8);
    ulonglong2 p0 = row[0], p1 = row[1];
    fma2(a0[0], p0.x, w0); fma2(a0[1], p0.y, w0);
    fma2(a0[2], p1.x, w0); fma2(a0[3], p1.y, w0);
    fma2(a1[0], p0.x, w1); fma2(a1[1], p0.y, w1);
    fma2(a1[2], p1.x, w1); fma2(a1[3], p1.y, w1);
}
__device__ __forceinline__ void accum1(ull a[4], const float* in_buf, int k, ull w2) {
    const ulonglong2* row = reinterpret_cast<const ulonglong2*>(in_buf + k * 8);
    ulonglong2 p0 = row[0], p1 = row[1];
    fma2(a[0], p0.x, w2); fma2(a[1], p0.y, w2);
    fma2(a[2], p1.x, w2); fma2(a[3], p1.y, w2);
}

// 2-column GEMM partial, adjacent cols (j2, j2+1), weights via float2, 8-deep prefetch.
// KS multiple of 8, >= 16. j2 must be even and j2+1 < N of the weight matrix.
__device__ __forceinline__ void gaccum2(float v0[8], float v1[8], const float* in_buf,
                                        const float* __restrict__ W, int ldw,
                                        int j2, int k0, int KS) {
    ull a0[4], a1[4];
    #pragma unroll
    for (int p = 0; p < 4; ++p) { a0[p] = 0ULL; a1[p] = 0ULL; }
    const int wld = ldw >> 1;
    const float2* __restrict__ wp = reinterpret_cast<const float2*>(W) + (size_t)k0 * wld + (j2 >> 1);
    float2 w[8];
    #pragma unroll
    for (int u = 0; u < 8; ++u) w[u] = wp[(size_t)u * wld];
    wp += (size_t)8 * wld;
    for (int kk = 0; kk < KS - 8; kk += 8) {
        float2 wn[8];
        #pragma unroll
        for (int u = 0; u < 8; ++u) wn[u] = wp[(size_t)u * wld];
        wp += (size_t)8 * wld;
        #pragma unroll
        for (int u = 0; u < 8; ++u)
            accum2(a0, a1, in_buf, k0 + kk + u, packdup(w[u].x), packdup(w[u].y));
        #pragma unroll
        for (int u = 0; u < 8; ++u) w[u] = wn[u];
    }
    #pragma unroll
    for (int u = 0; u < 8; ++u)
        accum2(a0, a1, in_buf, k0 + KS - 8 + u, packdup(w[u].x), packdup(w[u].y));
    #pragma unroll
    for (int p = 0; p < 4; ++p) { unpack2(a0[p], v0[2*p], v0[2*p+1]); unpack2(a1[p], v1[2*p], v1[2*p+1]); }
}

// 1-column GEMM partial, 8-deep scalar weight prefetch. KS multiple of 8, >= 16.
__device__ __forceinline__ void gaccum1(float v[8], const float* in_buf,
                                        const float* __restrict__ W, int ldw,
                                        int j, int k0, int KS) {
    ull a[4];
    #pragma unroll
    for (int p = 0; p < 4; ++p) a[p] = 0ULL;
    const float* __restrict__ wp = W + (size_t)k0 * ldw + j;
    float w[8];
    #pragma unroll
    for (int u = 0; u < 8; ++u) w[u] = wp[(size_t)u * ldw];
    wp += (size_t)8 * ldw;
    for (int kk = 0; kk < KS - 8; kk += 8) {
        float wn[8];
        #pragma unroll
        for (int u = 0; u < 8; ++u) wn[u] = wp[(size_t)u * ldw];
        wp += (size_t)8 * ldw;
        #pragma unroll
        for (int u = 0; u < 8; ++u) accum1(a, in_buf, k0 + kk + u, packdup(w[u]));
        #pragma unroll
        for (int u = 0; u < 8; ++u) w[u] = wn[u];
    }
    #pragma unroll
    for (int u = 0; u < 8; ++u) accum1(a, in_buf, k0 + KS - 8 + u, packdup(w[u]));
    #pragma unroll
    for (int p = 0; p < 4; ++p) unpack2(a[p], v[2*p], v[2*p+1]);
}

// warp-level reduce of 8 per-row partials; lane 0 holds sums
__device__ __forceinline__ void warp_reduce8(float sq[8]) {
    #pragma unroll
    for (int off = 16; off > 0; off >>= 1) {
        #pragma unroll
        for (int m = 0; m < 8; ++m)
            sq[m] += __shfl_down_sync(0xffffffffu, sq[m], off);
    }
}

__global__ void __launch_bounds__(NTHR, 2)
node_kernel(const float* __restrict__ y0, const float* __restrict__ tv,
            const float* __restrict__ noise,
            const float* __restrict__ fw1, const float* __restrict__ fb1,
            const float* __restrict__ fw2, const float* __restrict__ fb2,
            const float* __restrict__ fw3, const float* __restrict__ fb3,
            const float* __restrict__ amw1, const float* __restrict__ amb1,
            const float* __restrict__ amw2, const float* __restrict__ amb2,
            const float* __restrict__ amw3, const float* __restrict__ amb3,
            const float* __restrict__ alw1, const float* __restrict__ alb1,
            const float* __restrict__ alw2, const float* __restrict__ alb2,
            const float* __restrict__ alw3, const float* __restrict__ alb3,
            const float* __restrict__ kw, float* __restrict__ out)
{
    extern __shared__ float smem[];
    float* xs   = smem;              // 1024  [128][8]
    float* h1   = xs + 1024;         // 2048  [256][8]
    float* h2   = h1 + 2048;         // 2048
    float* fo   = h2 + 2048;         // 1024
    float* ko   = fo + 1024;         // 1024
    float* mo   = ko + 1024;         // 1024
    float* lso  = mo + 1024;         // 1024
    float* go   = lso + 1024;        // 1024  (f+g)
    float* ubf  = go + 1024;         // 1024
    float* ubg  = ubf + 1024;        // 1024
    float* a1m  = ubg + 1024;        // 512   [64][8]
    float* a1l  = a1m + 512;         // 512
    float* a2m  = a1l + 512;         // 512
    float* a2l  = a2m + 512;         // 512
    float* cb   = a2l + 512;         // 2048  combine scratch [256][8]
    float* redk = cb + 2048;         // 16
    float* redf = redk + 16;         // 32
    float* redg = redf + 32;         // 32
    float* kn2s = redg + 32;         // 8

    const int tid = threadIdx.x;
    const int r0 = blockIdx.x * MROWS;
    const float dt = tv[1] - tv[0];
    const int ewj = tid & 127;       // elementwise: col j
    const int ewc = tid >> 7;        // elementwise: chunk c (0/1), rows 4c..4c+3

    // load y0 tile (transposed [128][8]); emit output step 0
    {
        float a[4];
        #pragma unroll
        for (int q = 0; q < 4; ++q) {
            int m = 4 * ewc + q;
            float val = y0[(size_t)(r0 + m) * ND + ewj];
            out[(size_t)(r0 + m) * ND + ewj] = val;
            a[q] = val;
        }
        reinterpret_cast<float4*>(xs + ewj * 8)[ewc] = make_float4(a[0], a[1], a[2], a[3]);
    }
    __syncthreads();

    for (int step = 0; step < NSTEPS; ++step) {
        float v0[8], v1[8];
        // noise prefetch (consumed in stage E)
        float nse[4];
        {
            const float* np = noise + (size_t)step * BSZ * ND + (size_t)(r0 + 4 * ewc) * ND + ewj;
            #pragma unroll
            for (int q = 0; q < 4; ++q) nse[q] = np[(size_t)q * ND];
        }

        // ======== Stage A: f1(128thr,2col) || k(64thr,2col) || am1(32thr,2col) || al1(32thr,2col) ========
        if (tid < 128) {
            int j2 = 2 * tid;
            gaccum2(v0, v1, xs, fw1, HID, j2, 0, ND);
            float2 b = reinterpret_cast<const float2*>(fb1)[tid];
            #pragma unroll
            for (int m = 0; m < 8; ++m) { v0[m] = tanhf(v0[m] + b.x); v1[m] = tanhf(v1[m] + b.y); }
            store_row8(h1, j2, v0); store_row8(h1, j2 + 1, v1);
        } else if (tid < 192) {
            int t = tid - 128, j2 = 2 * t;
            gaccum2(v0, v1, xs, kw, ND, j2, 0, ND);
            float sq[8];
            #pragma unroll
            for (int m = 0; m < 8; ++m) {
                v0[m] = tanhf(v0[m]); v1[m] = tanhf(v1[m]);
                sq[m] = v0[m] * v0[m] + v1[m] * v1[m];
            }
            store_row8(ko, j2, v0); store_row8(ko, j2 + 1, v1);
            warp_reduce8(sq);
            if ((tid & 31) == 0) {
                int w = (tid - 128) >> 5;
                #pragma unroll
                for (int m = 0; m < 8; ++m) redk[w * 8 + m] = sq[m];
            }
        } else if (tid < 224) {
            int t = tid - 192, j2 = 2 * t;      // j2 in 0..62 -> 64 cols of amw1
            gaccum2(v0, v1, xs, amw1, SHD, j2, 0, ND);
            float2 b = reinterpret_cast<const float2*>(amb1)[t];
            #pragma unroll
            for (int m = 0; m < 8; ++m) { v0[m] = fmaxf(v0[m] + b.x, 0.f); v1[m] = fmaxf(v1[m] + b.y, 0.f); }
            store_row8(a1m, j2, v0); store_row8(a1m, j2 + 1, v1);
        } else {
            int t = tid - 224, j2 = 2 * t;
            gaccum2(v0, v1, xs, alw1, SHD, j2, 0, ND);
            float2 b = reinterpret_cast<const float2*>(alb1)[t];
            #pragma unroll
            for (int m = 0; m < 8; ++m) { v0[m] = fmaxf(v0[m] + b.x, 0.f); v1[m] = fmaxf(v1[m] + b.y, 0.f); }
            store_row8(a1l, j2, v0); store_row8(a1l, j2 + 1, v1);
        }
        __syncthreads();

        // ======== Stage B: f2 (2 cols/thread, K split over 2 halves) ========
        {
            int t = tid & 127, s = tid >> 7, j2 = 2 * t;
            gaccum2(v0, v1, h1, fw2, HID, j2, s * 128, 128);
            if (s == 1) { store_row8(cb, j2, v0); store_row8(cb, j2 + 1, v1); }
        }
        __syncthreads();
        {
            int t = tid & 127, s = tid >> 7, j2 = 2 * t;
            if (s == 0) {
                float w0[8], w1[8];
                load_row8(cb, j2, w0); load_row8(cb, j2 + 1, w1);
                float2 b = reinterpret_cast<const float2*>(fb2)[t];
                #pragma unroll
                for (int m = 0; m < 8; ++m) {
                    v0[m] = softplus_f(v0[m] + w0[m] + b.x);
                    v1[m] = softplus_f(v1[m] + w1[m] + b.y);
                }
                store_row8(h2, j2, v0); store_row8(h2, j2 + 1, v1);
            }
            if (tid < 8) kn2s[tid] = redk[tid] + redk[8 + tid];
        }
        __syncthreads();

        // ======== Stage C p1: f3 (128thr, full K=256) || am2 (64thr, 1col) || al2 (64thr, 1col) ========
        if (tid < 128) {
            gaccum1(v0, h2, fw3, ND, tid, 0, HID);
            float b = fb3[tid];
            #pragma unroll
            for (int m = 0; m < 8; ++m) v0[m] += b;
            store_row8(fo, tid, v0);
        } else if (tid < 192) {
            int j = tid - 128;                  // 64 cols, one each
            gaccum1(v0, a1m, amw2, SHD, j, 0, SHD);
            float b = amb2[j];
            #pragma unroll
            for (int m = 0; m < 8; ++m) v0[m] = fmaxf(v0[m] + b, 0.f);
            store_row8(a2m, j, v0);
        } else {
            int j = tid - 192;
            gaccum1(v0, a1l, alw2, SHD, j, 0, SHD);
            float b = alb2[j];
            #pragma unroll
            for (int m = 0; m < 8; ++m) v0[m] = fmaxf(v0[m] + b, 0.f);
            store_row8(a2l, j, v0);
        }
        __syncthreads();

        // ======== Stage C p2: am3 (128thr) || al3 (128thr) ========
        if (tid < 128) {
            gaccum1(v0, a2m, amw3, ND, tid, 0, SHD);
            float b = amb3[tid];
            #pragma unroll
            for (int m = 0; m < 8; ++m) v0[m] = tanhf(v0[m] + b);
            store_row8(mo, tid, v0);
        } else {
            int j = tid - 128;
            gaccum1(v0, a2l, alw3, ND, j, 0, SHD);
            float b = alb3[j];
            #pragma unroll
            for (int m = 0; m < 8; ++m) v0[m] += b;
            store_row8(lso, j, v0);
        }
        __syncthreads();

        // ======== Stage E: g, f+g, u_f, u_g (elementwise float4) ========
        {
            float4 kv = reinterpret_cast<const float4*>(ko + ewj * 8)[ewc];
            float4 fv = reinterpret_cast<const float4*>(fo + ewj * 8)[ewc];
            float4 mv = reinterpret_cast<const float4*>(mo + ewj * 8)[ewc];
            float4 lv = reinterpret_cast<const float4*>(lso + ewj * 8)[ewc];
            float kk[4] = {kv.x, kv.y, kv.z, kv.w};
            float ff[4] = {fv.x, fv.y, fv.z, fv.w};
            float mm[4] = {mv.x, mv.y, mv.z, mv.w};
            float ll[4] = {lv.x, lv.y, lv.z, lv.w};
            float gs[4], uf[4], ug[4];
            #pragma unroll
            for (int q = 0; q < 4; ++q) {
                float sd = softplus_f(san(ll[q]));
                float g = tanhf(san(mm[q]) + sd * nse[q]);
                float om = 1.f - kk[q] * kk[q];
                gs[q] = ff[q] + g;
                uf[q] = om * ff[q];
                ug[q] = om * g;
            }
            reinterpret_cast<float4*>(go + ewj * 8)[ewc] = make_float4(gs[0], gs[1], gs[2], gs[3]);
            reinterpret_cast<float4*>(ubf + ewj * 8)[ewc] = make_float4(uf[0], uf[1], uf[2], uf[3]);
            reinterpret_cast<float4*>(ubg + ewj * 8)[ewc] = make_float4(ug[0], ug[1], ug[2], ug[3]);
        }
        __syncthreads();

        // ======== Stage F: jacf (128thr) || jacg (128thr), direct global kw ========
        if (tid < 128) {
            gaccum1(v0, ubf, kw, ND, tid, 0, ND);
            float sq[8];
            #pragma unroll
            for (int m = 0; m < 8; ++m) sq[m] = v0[m] * v0[m];
            warp_reduce8(sq);
            if ((tid & 31) == 0) {
                int w = tid >> 5;
                #pragma unroll
                for (int m = 0; m < 8; ++m) redf[w * 8 + m] = sq[m];
            }
        } else {
            int j = tid - 128;
            gaccum1(v0, ubg, kw, ND, j, 0, ND);
            float kr[8];
            load_row8(ko, j, kr);
            float sq[8];
            #pragma unroll
            for (int m = 0; m < 8; ++m) sq[m] = v0[m] * kr[m];
            warp_reduce8(sq);
            if ((tid & 31) == 0) {
                int w = (tid - 128) >> 5;
                #pragma unroll
                for (int m = 0; m < 8; ++m) redg[w * 8 + m] = sq[m];
            }
        }
        __syncthreads();

        // ======== Update: inline mask + Euler + output ========
        {
            float sclq[4];
            #pragma unroll
            for (int q = 0; q < 4; ++q) {
                int m = 4 * ewc + q;
                float kn2 = kn2s[m];
                float jf2 = redf[m] + redf[8 + m] + redf[16 + m] + redf[24 + m];
                float c2v = redg[m] + redg[8 + m] + redg[16 + m] + redg[24 + m];
                float kn = sqrtf(kn2);
                float kn9 = kn2 * kn2 * kn2 * kn2 * kn;
                float c1 = sqrtf(jf2) - 60.0f * kn9;
                float c2 = c2v - 20.0f * kn9 * kn;
                bool mask = (c1 > 1e-8f) || (c2 < -1e-8f);
                sclq[q] = mask ? (0.5f * dt) : dt;
            }
            float4 xv = reinterpret_cast<const float4*>(xs + ewj * 8)[ewc];
            float4 dv = reinterpret_cast<const float4*>(go + ewj * 8)[ewc];
            float x[4] = {xv.x, xv.y, xv.z, xv.w};
            float d[4] = {dv.x, dv.y, dv.z, dv.w};
            float o[4];
            float* ob = out + (size_t)(step + 1) * BSZ * ND;
            #pragma unroll
            for (int q = 0; q < 4; ++q) {
                int m = 4 * ewc + q;
                o[q] = x[q] + d[q] * sclq[q];
                ob[(size_t)(r0 + m) * ND + ewj] = o[q];
            }
            reinterpret_cast<float4*>(xs + ewj * 8)[ewc] = make_float4(o[0], o[1], o[2], o[3]);
        }
        __syncthreads();
    }
}

extern "C" void kernel_launch(void* const* d_in, const int* in_sizes, int n_in,
                              void* d_out, int out_size) {
    (void)in_sizes; (void)n_in; (void)out_size;
    const float* y0   = (const float*)d_in[0];
    const float* tv   = (const float*)d_in[1];
    const float* nz   = (const float*)d_in[2];
    const float* fw1  = (const float*)d_in[3];
    const float* fb1  = (const float*)d_in[4];
    const float* fw2  = (const float*)d_in[5];
    const float* fb2  = (const float*)d_in[6];
    const float* fw3  = (const float*)d_in[7];
    const float* fb3  = (const float*)d_in[8];
    const float* amw1 = (const float*)d_in[9];
    const float* amb1 = (const float*)d_in[10];
    const float* amw2 = (const float*)d_in[11];
    const float* amb2 = (const float*)d_in[12];
    const float* amw3 = (const float*)d_in[13];
    const float* amb3 = (const float*)d_in[14];
    const float* alw1 = (const float*)d_in[15];
    const float* alb1 = (const float*)d_in[16];
    const float* alw2 = (const float*)d_in[17];
    const float* alb2 = (const float*)d_in[18];
    const float* alw3 = (const float*)d_in[19];
    const float* alb3 = (const float*)d_in[20];
    const float* kw   = (const float*)d_in[21];
    float* out = (float*)d_out;

    const int shmem = 16472 * sizeof(float);  // ~65.9 KB -> 2 blocks/SM
    cudaFuncSetAttribute(node_kernel, cudaFuncAttributeMaxDynamicSharedMemorySize, shmem);
    node_kernel<<<NBLOCKS, NTHR, shmem>>>(
        y0, tv, nz, fw1, fb1, fw2, fb2, fw3, fb3,
        amw1, amb1, amw2, amb2, amw3, amb3,
        alw1, alb1, alw2, alb2, alw3, alb3, kw, out);
}